// round 15
// baseline (speedup 1.0000x reference)
#include <cuda_runtime.h>
#include <cuda_bf16.h>
#include <cstdint>

// Problem constants (fixed shapes for TrivialDecoder_1236950581455)
#define E_GROUPS 65536
#define KNEG     16
#define GROUP    17
#define PAIRS    (E_GROUPS * GROUP)   // 1,114,112
#define D        64
#define KDIM     192
#define M_TILE   128
#define NTILE_TOT (PAIRS / M_TILE)    // 8704
#define THREADS  256                  // 8 warps, each owns 16 m-rows
#define KSTEPS   6                    // 192 / 32 (fp8 k32 mma)
#define NTILES   8                    // 64 / 8
#define GRID_SC  296                  // 148 SMs x 2 CTAs

#define APITCH   208                  // A: bytes per row (e4m3), conflict-free LDS
#define ASIZE    (128 * APITCH)       // 26624 per A buffer

// SMEM byte layout: total 66560 B -> 2 CTAs/SM (double-buffered A)
#define SMEM_B1    0                          // 64 floats
#define SMEM_W2    256                        // 64 floats
#define SMEM_A0    1024
#define SMEM_B     (1024 + 2 * ASIZE)         // packed B: 1536 x 8 = 12288 B
#define SMEM_TOTAL (SMEM_B + 12288)           // 66560

__device__ float g_scores[PAIRS];

__global__ void zero_out_kernel(float* out) { out[0] = 0.0f; }

// ---------------- portable PTX helpers ----------------
__device__ __forceinline__ uint32_t pack4_e4m3(float x0, float x1, float x2, float x3) {
    uint16_t lo, hi;
    asm("cvt.rn.satfinite.e4m3x2.f32 %0, %1, %2;" : "=h"(lo) : "f"(x1), "f"(x0));
    asm("cvt.rn.satfinite.e4m3x2.f32 %0, %1, %2;" : "=h"(hi) : "f"(x3), "f"(x2));
    return (uint32_t)lo | ((uint32_t)hi << 16);
}

__device__ __forceinline__ void mma_16832_e4m3(float* c, const uint32_t* a,
                                               uint32_t b0, uint32_t b1) {
    asm volatile(
        "mma.sync.aligned.m16n8k32.row.col.f32.e4m3.e4m3.f32 "
        "{%0,%1,%2,%3}, {%4,%5,%6,%7}, {%8,%9}, {%0,%1,%2,%3};"
        : "+f"(c[0]), "+f"(c[1]), "+f"(c[2]), "+f"(c[3])
        : "r"(a[0]), "r"(a[1]), "r"(a[2]), "r"(a[3]), "r"(b0), "r"(b1));
}

// ---------------------------------------------------------------------------
// Kernel 1: persistent, barrier-free warp pipelines; 8 warps x 16 m-rows.
// SOFTWARE-PIPELINED gather: tile t+G's LDGs are issued before/between the
// two GEMM halves of tile t, hiding DRAM latency under mma work. A tile is
// double-buffered in shared. B (W1) packed (8B LDS per fragment). fp8 mma.
// ---------------------------------------------------------------------------
__global__ void __launch_bounds__(THREADS, 2)
score_kernel(const float* __restrict__ embeds,
             const int*   __restrict__ pos,
             const int*   __restrict__ neg,
             const float* __restrict__ W1,
             const float* __restrict__ b1,
             const float* __restrict__ W2,
             const float* __restrict__ b2)
{
    extern __shared__ char smem[];
    const int tid = threadIdx.x;
    const int wid = tid >> 5;
    const int lid = tid & 31;
    const int g   = lid >> 2;          // fragment row/col group
    const int tg  = lid & 3;           // thread-in-group

    // One-time staging: b1, W2 to shared.
    if (tid < 64) {
        ((float*)(smem + SMEM_B1))[tid] = b1[tid];
        ((float*)(smem + SMEM_W2))[tid] = W2[tid];
    }
    // Stage W1 as PACKED e4m3 fragment entries (scaled x8).
    for (int c = tid; c < 64 * 24; c += THREADS) {
        int n   = c / 24;
        int rem = c - n * 24;
        int ks  = rem >> 2;
        int tt  = rem & 3;
        int nt  = n >> 3;
        int gg  = n & 7;
        const float4* wp0 = (const float4*)(W1 + n * KDIM + ks * 32 + tt * 4);
        const float4* wp1 = (const float4*)(W1 + n * KDIM + ks * 32 + 16 + tt * 4);
        float4 w0 = *wp0, w1 = *wp1;
        uint2 v = make_uint2(
            pack4_e4m3(w0.x * 8.0f, w0.y * 8.0f, w0.z * 8.0f, w0.w * 8.0f),
            pack4_e4m3(w1.x * 8.0f, w1.y * 8.0f, w1.z * 8.0f, w1.w * 8.0f));
        int e = ((nt * 6 + ks) * 8 + gg) * 4 + tt;
        *(uint2*)(smem + SMEM_B + e * 8) = v;
    }
    __syncthreads();   // only block barrier in the kernel

    const float b2v = b2[0];
    const int q   = lid & 15;          // float4 slot within a 64-float row
    const int grp = lid >> 4;          // which of two rows per gather iter

    // ---- index loader (lanes 0..15 meaningful) ----
    auto load_idx = [&](int tile, int& iu, int& iv) {
        iu = 0; iv = 0;
        if (lid < 16) {
            int p = tile * M_TILE + wid * 16 + lid;
            unsigned e = (unsigned)p / 17u;
            unsigned jj = (unsigned)p - e * 17u;
            const int* pr = (jj == 0) ? (pos + 2 * e)
                                      : (neg + 2 * (e * KNEG + (jj - 1)));
            iu = pr[0];
            iv = pr[1];
        }
    };
    // ---- gather one half (4 row-pair iterations) into fp32 regs ----
    auto gather_half = [&](int h, int iu_r, int iv_r, float4* ub, float4* vb) {
        #pragma unroll
        for (int i = 0; i < 4; i++) {
            int src = 2 * (h * 4 + i) + grp;
            int iu = __shfl_sync(0xffffffffu, iu_r, src);
            int iv = __shfl_sync(0xffffffffu, iv_r, src);
            ub[i] = ((const float4*)(embeds + (size_t)iu * 64))[q];
            vb[i] = ((const float4*)(embeds + (size_t)iv * 64))[q];
        }
    };
    // ---- convert+store one half into A buffer `ab` ----
    auto convert_half = [&](int h, const float4* ub, const float4* vb, char* ab) {
        #pragma unroll
        for (int i = 0; i < 4; i++) {
            int src = 2 * (h * 4 + i) + grp;
            float4 u4 = ub[i], v4 = vb[i];
            char* xr = ab + (wid * 16 + src) * APITCH;
            *(uint32_t*)(xr + q * 4) =
                pack4_e4m3(u4.x, u4.y, u4.z, u4.w);
            *(uint32_t*)(xr + 64 + q * 4) =
                pack4_e4m3(v4.x, v4.y, v4.z, v4.w);
            *(uint32_t*)(xr + 128 + q * 4) =
                pack4_e4m3(u4.x * v4.x, u4.y * v4.y, u4.z * v4.z, u4.w * v4.w);
        }
    };

    // ---- pipeline prologue: fill A buffer 0 with tile t0; prefetch idx ----
    int t = blockIdx.x;
    int pb = 0;
    {
        int iu0, iv0;
        load_idx(t, iu0, iv0);
        float4 ub[4], vb[4];
        gather_half(0, iu0, iv0, ub, vb);
        convert_half(0, ub, vb, smem + SMEM_A0);
        gather_half(1, iu0, iv0, ub, vb);
        convert_half(1, ub, vb, smem + SMEM_A0);
    }
    int tn1 = (t + GRID_SC < NTILE_TOT) ? t + GRID_SC : t;
    int iun, ivn;
    load_idx(tn1, iun, ivn);
    __syncwarp();

    for (; t < NTILE_TOT; t += GRID_SC) {
        const int p0 = t * M_TILE;
        char* a_cur = smem + SMEM_A0 + pb * ASIZE;
        char* a_nxt = smem + SMEM_A0 + (pb ^ 1) * ASIZE;

        // 1. issue idx load for t+2G (consumed next iteration)
        int t2 = (t + 2 * GRID_SC < NTILE_TOT) ? t + 2 * GRID_SC : t;
        int iu2, iv2;
        load_idx(t2, iu2, iv2);

        // 2. issue gather LDGs for half0 of t+G
        float4 ub[4], vb[4];
        gather_half(0, iun, ivn, ub, vb);

        // 3. GEMM part1 (ks 0..2) on tile t — covers half0 latency
        float c0[NTILES][4];
        #pragma unroll
        for (int nt = 0; nt < NTILES; nt++) {
            c0[nt][0] = c0[nt][1] = c0[nt][2] = c0[nt][3] = 0.0f;
        }
        #pragma unroll
        for (int ks = 0; ks < 3; ks++) {
            uint32_t a0[4];
            {
                const char* ar = a_cur + (wid * 16 + g) * APITCH + ks * 32 + tg * 4;
                a0[0] = *(const uint32_t*)(ar);
                a0[1] = *(const uint32_t*)(ar + 8 * APITCH);
                a0[2] = *(const uint32_t*)(ar + 16);
                a0[3] = *(const uint32_t*)(ar + 8 * APITCH + 16);
            }
            #pragma unroll
            for (int nt = 0; nt < NTILES; nt++) {
                uint2 b = *(const uint2*)(smem + SMEM_B
                                          + ((nt * 6 + ks) * 32 + lid) * 8);
                mma_16832_e4m3(c0[nt], a0, b.x, b.y);
            }
        }

        // 4. convert+STS half0 of t+G into the other A buffer
        convert_half(0, ub, vb, a_nxt);

        // 5. issue gather LDGs for half1 of t+G
        gather_half(1, iun, ivn, ub, vb);

        // 6. GEMM part2 (ks 3..5) — covers half1 latency
        #pragma unroll
        for (int ks = 3; ks < KSTEPS; ks++) {
            uint32_t a0[4];
            {
                const char* ar = a_cur + (wid * 16 + g) * APITCH + ks * 32 + tg * 4;
                a0[0] = *(const uint32_t*)(ar);
                a0[1] = *(const uint32_t*)(ar + 8 * APITCH);
                a0[2] = *(const uint32_t*)(ar + 16);
                a0[3] = *(const uint32_t*)(ar + 8 * APITCH + 16);
            }
            #pragma unroll
            for (int nt = 0; nt < NTILES; nt++) {
                uint2 b = *(const uint2*)(smem + SMEM_B
                                          + ((nt * 6 + ks) * 32 + lid) * 8);
                mma_16832_e4m3(c0[nt], a0, b.x, b.y);
            }
        }

        // 7. epilogue (x0.125 undoes the W1 x8 scale)
        {
            const float* b1s = (const float*)(smem + SMEM_B1);
            const float* w2s = (const float*)(smem + SMEM_W2);
            float z0 = 0.0f, z1 = 0.0f;
            #pragma unroll
            for (int nt = 0; nt < NTILES; nt++) {
                int n0 = nt * 8 + 2 * tg;
                float bb0 = b1s[n0], bb1 = b1s[n0 + 1];
                float ww0 = w2s[n0], ww1 = w2s[n0 + 1];
                float h;
                h = fmaf(c0[nt][0], 0.125f, bb0); h = h > 0.0f ? h : 0.0f; z0 += h * ww0;
                h = fmaf(c0[nt][1], 0.125f, bb1); h = h > 0.0f ? h : 0.0f; z0 += h * ww1;
                h = fmaf(c0[nt][2], 0.125f, bb0); h = h > 0.0f ? h : 0.0f; z1 += h * ww0;
                h = fmaf(c0[nt][3], 0.125f, bb1); h = h > 0.0f ? h : 0.0f; z1 += h * ww1;
            }
            z0 += __shfl_xor_sync(0xffffffffu, z0, 1);
            z0 += __shfl_xor_sync(0xffffffffu, z0, 2);
            z1 += __shfl_xor_sync(0xffffffffu, z1, 1);
            z1 += __shfl_xor_sync(0xffffffffu, z1, 2);
            if (tg == 0) {
                int r = p0 + wid * 16 + g;
                float s0 = 1.0f / (1.0f + expf(-(z0 + b2v)));
                float s1 = 1.0f / (1.0f + expf(-(z1 + b2v)));
                g_scores[r]     = expf(s0);
                g_scores[r + 8] = expf(s1);
            }
        }

        // 8. convert+STS half1 of t+G
        convert_half(1, ub, vb, a_nxt);

        __syncwarp();   // order STS (steps 4/8) before next iter's fragment LDS
        iun = iu2; ivn = iv2; pb ^= 1;
    }
}

// ---------------------------------------------------------------------------
// Kernel 2: per-group ratio + global reduction.
// ---------------------------------------------------------------------------
__global__ void __launch_bounds__(256)
loss_kernel(float* __restrict__ out)
{
    int e = blockIdx.x * blockDim.x + threadIdx.x;
    float term = 0.0f;
    if (e < E_GROUPS) {
        const float* s = g_scores + (long long)e * GROUP;
        float ps = s[0];
        float denom = ps;
        #pragma unroll
        for (int j = 1; j < GROUP; j++) denom += s[j];
        term = ps / (denom + 1e-8f) + 1e-8f;
    }
    #pragma unroll
    for (int o = 16; o; o >>= 1) term += __shfl_xor_sync(0xffffffffu, term, o);

    __shared__ float wsum[8];
    int l = threadIdx.x & 31;
    int w = threadIdx.x >> 5;
    if (l == 0) wsum[w] = term;
    __syncthreads();
    if (threadIdx.x < 8) {
        float t = wsum[threadIdx.x];
        #pragma unroll
        for (int o = 4; o; o >>= 1) t += __shfl_xor_sync(0x000000ffu, t, o);
        if (threadIdx.x == 0) atomicAdd(out, -t);
    }
}

extern "C" void kernel_launch(void* const* d_in, const int* in_sizes, int n_in,
                              void* d_out, int out_size)
{
    const float* embeds = (const float*)d_in[0];
    const int*   pos    = (const int*)  d_in[1];
    const int*   neg    = (const int*)  d_in[2];
    const float* W1     = (const float*)d_in[3];
    const float* b1     = (const float*)d_in[4];
    const float* W2     = (const float*)d_in[5];
    const float* b2     = (const float*)d_in[6];
    float*       out    = (float*)d_out;

    cudaFuncSetAttribute(score_kernel, cudaFuncAttributeMaxDynamicSharedMemorySize,
                         SMEM_TOTAL);

    score_kernel<<<GRID_SC, THREADS, SMEM_TOTAL>>>(embeds, pos, neg, W1, b1, W2, b2);
    zero_out_kernel<<<1, 1>>>(out);
    loss_kernel<<<E_GROUPS / 256, 256>>>(out);
}

// round 16
// speedup vs baseline: 1.2021x; 1.2021x over previous
#include <cuda_runtime.h>
#include <cuda_bf16.h>
#include <cstdint>

// Problem constants (fixed shapes for TrivialDecoder_1236950581455)
#define E_GROUPS 65536
#define KNEG     16
#define GROUP    17
#define PAIRS    (E_GROUPS * GROUP)   // 1,114,112
#define D        64
#define KDIM     192
#define M_TILE   128
#define NTILE_TOT (PAIRS / M_TILE)    // 8704
#define THREADS  256                  // 8 warps, each owns 16 m-rows
#define KSTEPS   6                    // 192 / 32 (fp8 k32 mma)
#define NTILES   8                    // 64 / 8
#define GRID_SC  444                  // 148 SMs x 3 CTAs

#define APITCH   208                  // A: bytes per row (e4m3), conflict-free LDS

// SMEM byte layout: total 39936 B -> 3 CTAs/SM
#define SMEM_B1    0                          // 64 floats
#define SMEM_W2    256                        // 64 floats
#define SMEM_A     1024                       // 128 x 208 = 26624 B
#define SMEM_B     (1024 + 128 * APITCH)      // packed B: 1536 x 8 = 12288 B
#define SMEM_TOTAL (SMEM_B + 12288)           // 39936

__device__ float g_scores[PAIRS];

__global__ void zero_out_kernel(float* out) { out[0] = 0.0f; }

// ---------------- portable PTX helpers ----------------
__device__ __forceinline__ uint32_t pack4_e4m3(float x0, float x1, float x2, float x3) {
    uint16_t lo, hi;
    asm("cvt.rn.satfinite.e4m3x2.f32 %0, %1, %2;" : "=h"(lo) : "f"(x1), "f"(x0));
    asm("cvt.rn.satfinite.e4m3x2.f32 %0, %1, %2;" : "=h"(hi) : "f"(x3), "f"(x2));
    return (uint32_t)lo | ((uint32_t)hi << 16);
}

__device__ __forceinline__ void mma_16832_e4m3(float* c, const uint32_t* a,
                                               uint32_t b0, uint32_t b1) {
    asm volatile(
        "mma.sync.aligned.m16n8k32.row.col.f32.e4m3.e4m3.f32 "
        "{%0,%1,%2,%3}, {%4,%5,%6,%7}, {%8,%9}, {%0,%1,%2,%3};"
        : "+f"(c[0]), "+f"(c[1]), "+f"(c[2]), "+f"(c[3])
        : "r"(a[0]), "r"(a[1]), "r"(a[2]), "r"(a[3]), "r"(b0), "r"(b1));
}

__device__ __forceinline__ void prefetch_l2(const void* p) {
    asm volatile("prefetch.global.L2 [%0];" :: "l"(p));
}

// ---------------------------------------------------------------------------
// Kernel 1: persistent, barrier-free warp pipelines; 8 warps x 16 m-rows.
// R13 base (125.4us) + register-free latency removal:
//  - index double-buffer: current tile's indices were LDG'd last iteration
//  - prefetch.global.L2 of the NEXT tile's embedding rows (fire-and-forget)
// B (W1) packed in shared (8B LDS per fragment). fp8 mma, fp32 accumulate.
// ---------------------------------------------------------------------------
__global__ void __launch_bounds__(THREADS, 3)
score_kernel(const float* __restrict__ embeds,
             const int*   __restrict__ pos,
             const int*   __restrict__ neg,
             const float* __restrict__ W1,
             const float* __restrict__ b1,
             const float* __restrict__ W2,
             const float* __restrict__ b2)
{
    extern __shared__ char smem[];
    const int tid = threadIdx.x;
    const int wid = tid >> 5;
    const int lid = tid & 31;
    const int g   = lid >> 2;          // fragment row/col group
    const int tg  = lid & 3;           // thread-in-group

    // One-time staging: b1, W2 to shared.
    if (tid < 64) {
        ((float*)(smem + SMEM_B1))[tid] = b1[tid];
        ((float*)(smem + SMEM_W2))[tid] = W2[tid];
    }
    // Stage W1 as PACKED e4m3 fragment entries (scaled x8).
    for (int c = tid; c < 64 * 24; c += THREADS) {
        int n   = c / 24;
        int rem = c - n * 24;
        int ks  = rem >> 2;
        int tt  = rem & 3;
        int nt  = n >> 3;
        int gg  = n & 7;
        const float4* wp0 = (const float4*)(W1 + n * KDIM + ks * 32 + tt * 4);
        const float4* wp1 = (const float4*)(W1 + n * KDIM + ks * 32 + 16 + tt * 4);
        float4 w0 = *wp0, w1 = *wp1;
        uint2 v = make_uint2(
            pack4_e4m3(w0.x * 8.0f, w0.y * 8.0f, w0.z * 8.0f, w0.w * 8.0f),
            pack4_e4m3(w1.x * 8.0f, w1.y * 8.0f, w1.z * 8.0f, w1.w * 8.0f));
        int e = ((nt * 6 + ks) * 8 + gg) * 4 + tt;
        *(uint2*)(smem + SMEM_B + e * 8) = v;
    }
    __syncthreads();   // only block barrier in the kernel

    const float b2v = b2[0];
    const int q   = lid & 15;          // float4 slot within a 64-float row
    const int grp = lid >> 4;          // which of two rows per gather iter

    // ---- index loader (lanes 0..15 meaningful) ----
    auto load_idx = [&](int tile, int& iu, int& iv) {
        iu = 0; iv = 0;
        if (lid < 16) {
            int p = tile * M_TILE + wid * 16 + lid;
            unsigned e = (unsigned)p / 17u;
            unsigned jj = (unsigned)p - e * 17u;
            const int* pr = (jj == 0) ? (pos + 2 * e)
                                      : (neg + 2 * (e * KNEG + (jj - 1)));
            iu = pr[0];
            iv = pr[1];
        }
    };

    // ---- pipeline prologue: indices for tile t0 (A) and t0+G (B) ----
    int t = blockIdx.x;
    int iuA, ivA, iuB, ivB;
    load_idx(t, iuA, ivA);
    {
        int tn = (t + GRID_SC < NTILE_TOT) ? t + GRID_SC : t;
        load_idx(tn, iuB, ivB);
    }

    for (; t < NTILE_TOT; t += GRID_SC) {
        const int p0 = t * M_TILE;

        // 0. prefetch next tile's rows into L2 (register-free, fire-and-forget)
        #pragma unroll
        for (int it = 0; it < 8; it++) {
            int src = 2 * it + grp;
            int iu = __shfl_sync(0xffffffffu, iuB, src);
            int iv = __shfl_sync(0xffffffffu, ivB, src);
            prefetch_l2(embeds + (size_t)iu * 64 + q * 4);
            prefetch_l2(embeds + (size_t)iv * 64 + q * 4);
        }

        // 1. issue idx load for t+2G (consumed next iteration as idxB)
        int iuC, ivC;
        {
            int t2 = (t + 2 * GRID_SC < NTILE_TOT) ? t + 2 * GRID_SC : t;
            load_idx(t2, iuC, ivC);
        }

        // 2. gather + convert current tile (indices already in registers)
        #pragma unroll
        for (int bt = 0; bt < 2; bt++) {
            float4 ub[4], vb[4];
            #pragma unroll
            for (int i = 0; i < 4; i++) {
                int src = 2 * (bt * 4 + i) + grp;           // local row 0..15
                int iu = __shfl_sync(0xffffffffu, iuA, src);
                int iv = __shfl_sync(0xffffffffu, ivA, src);
                ub[i] = ((const float4*)(embeds + (size_t)iu * 64))[q];
                vb[i] = ((const float4*)(embeds + (size_t)iv * 64))[q];
            }
            #pragma unroll
            for (int i = 0; i < 4; i++) {
                int src = 2 * (bt * 4 + i) + grp;
                float4 u4 = ub[i], v4 = vb[i];
                char* xr = smem + SMEM_A + (wid * 16 + src) * APITCH;
                *(uint32_t*)(xr + q * 4) =
                    pack4_e4m3(u4.x, u4.y, u4.z, u4.w);
                *(uint32_t*)(xr + 64 + q * 4) =
                    pack4_e4m3(v4.x, v4.y, v4.z, v4.w);
                *(uint32_t*)(xr + 128 + q * 4) =
                    pack4_e4m3(u4.x * v4.x, u4.y * v4.y, u4.z * v4.z, u4.w * v4.w);
            }
        }
        __syncwarp();   // order gather STS before cross-lane fragment LDS

        // 3. GEMM: warp tile 16(m) x 64(n), K=192; B via packed 8B LDS
        float c0[NTILES][4];
        #pragma unroll
        for (int nt = 0; nt < NTILES; nt++) {
            c0[nt][0] = c0[nt][1] = c0[nt][2] = c0[nt][3] = 0.0f;
        }
        #pragma unroll
        for (int ks = 0; ks < KSTEPS; ks++) {
            uint32_t a0[4];
            {
                const char* ar = smem + SMEM_A + (wid * 16 + g) * APITCH + ks * 32 + tg * 4;
                a0[0] = *(const uint32_t*)(ar);
                a0[1] = *(const uint32_t*)(ar + 8 * APITCH);
                a0[2] = *(const uint32_t*)(ar + 16);
                a0[3] = *(const uint32_t*)(ar + 8 * APITCH + 16);
            }
            #pragma unroll
            for (int nt = 0; nt < NTILES; nt++) {
                uint2 b = *(const uint2*)(smem + SMEM_B
                                          + ((nt * 6 + ks) * 32 + lid) * 8);
                mma_16832_e4m3(c0[nt], a0, b.x, b.y);
            }
        }

        // 4. epilogue in fragment layout (x0.125 undoes the W1 x8 scale)
        const float* b1s = (const float*)(smem + SMEM_B1);
        const float* w2s = (const float*)(smem + SMEM_W2);
        float z0 = 0.0f, z1 = 0.0f;
        #pragma unroll
        for (int nt = 0; nt < NTILES; nt++) {
            int n0 = nt * 8 + 2 * tg;
            float bb0 = b1s[n0], bb1 = b1s[n0 + 1];
            float ww0 = w2s[n0], ww1 = w2s[n0 + 1];
            float h;
            h = fmaf(c0[nt][0], 0.125f, bb0); h = h > 0.0f ? h : 0.0f; z0 += h * ww0;
            h = fmaf(c0[nt][1], 0.125f, bb1); h = h > 0.0f ? h : 0.0f; z0 += h * ww1;
            h = fmaf(c0[nt][2], 0.125f, bb0); h = h > 0.0f ? h : 0.0f; z1 += h * ww0;
            h = fmaf(c0[nt][3], 0.125f, bb1); h = h > 0.0f ? h : 0.0f; z1 += h * ww1;
        }
        z0 += __shfl_xor_sync(0xffffffffu, z0, 1);
        z0 += __shfl_xor_sync(0xffffffffu, z0, 2);
        z1 += __shfl_xor_sync(0xffffffffu, z1, 1);
        z1 += __shfl_xor_sync(0xffffffffu, z1, 2);

        if (tg == 0) {
            int r = p0 + wid * 16 + g;
            float s0 = 1.0f / (1.0f + expf(-(z0 + b2v)));
            float s1 = 1.0f / (1.0f + expf(-(z1 + b2v)));
            g_scores[r]     = expf(s0);
            g_scores[r + 8] = expf(s1);
        }

        // 5. rotate index buffers
        iuA = iuB; ivA = ivB; iuB = iuC; ivB = ivC;
    }
}

// ---------------------------------------------------------------------------
// Kernel 2: per-group ratio + global reduction.
// ---------------------------------------------------------------------------
__global__ void __launch_bounds__(256)
loss_kernel(float* __restrict__ out)
{
    int e = blockIdx.x * blockDim.x + threadIdx.x;
    float term = 0.0f;
    if (e < E_GROUPS) {
        const float* s = g_scores + (long long)e * GROUP;
        float ps = s[0];
        float denom = ps;
        #pragma unroll
        for (int j = 1; j < GROUP; j++) denom += s[j];
        term = ps / (denom + 1e-8f) + 1e-8f;
    }
    #pragma unroll
    for (int o = 16; o; o >>= 1) term += __shfl_xor_sync(0xffffffffu, term, o);

    __shared__ float wsum[8];
    int l = threadIdx.x & 31;
    int w = threadIdx.x >> 5;
    if (l == 0) wsum[w] = term;
    __syncthreads();
    if (threadIdx.x < 8) {
        float t = wsum[threadIdx.x];
        #pragma unroll
        for (int o = 4; o; o >>= 1) t += __shfl_xor_sync(0x000000ffu, t, o);
        if (threadIdx.x == 0) atomicAdd(out, -t);
    }
}

extern "C" void kernel_launch(void* const* d_in, const int* in_sizes, int n_in,
                              void* d_out, int out_size)
{
    const float* embeds = (const float*)d_in[0];
    const int*   pos    = (const int*)  d_in[1];
    const int*   neg    = (const int*)  d_in[2];
    const float* W1     = (const float*)d_in[3];
    const float* b1     = (const float*)d_in[4];
    const float* W2     = (const float*)d_in[5];
    const float* b2     = (const float*)d_in[6];
    float*       out    = (float*)d_out;

    cudaFuncSetAttribute(score_kernel, cudaFuncAttributeMaxDynamicSharedMemorySize,
                         SMEM_TOTAL);

    score_kernel<<<GRID_SC, THREADS, SMEM_TOTAL>>>(embeds, pos, neg, W1, b1, W2, b2);
    zero_out_kernel<<<1, 1>>>(out);
    loss_kernel<<<E_GROUPS / 256, 256>>>(out);
}

// round 17
// speedup vs baseline: 1.2763x; 1.0617x over previous
#include <cuda_runtime.h>
#include <cuda_bf16.h>
#include <cstdint>

// Problem constants (fixed shapes for TrivialDecoder_1236950581455)
#define E_GROUPS 65536
#define KNEG     16
#define GROUP    17
#define PAIRS    (E_GROUPS * GROUP)   // 1,114,112
#define D        64
#define KDIM     192
#define M_TILE   128
#define NTILE_TOT (PAIRS / M_TILE)    // 8704
#define THREADS  256                  // 8 warps, each owns 16 m-rows
#define KSTEPS   6                    // 192 / 32 (fp8 k32 mma)
#define NTILES   8                    // 64 / 8
#define GRID_SC  444                  // 148 SMs x 3 CTAs

#define APITCH   208                  // A: bytes per row (e4m3), conflict-free LDS

// SMEM byte layout: total 39936 B -> 3 CTAs/SM
#define SMEM_B1    0                          // 64 floats
#define SMEM_W2    256                        // 64 floats
#define SMEM_A     1024                       // 128 x 208 = 26624 B
#define SMEM_B     (1024 + 128 * APITCH)      // packed B: 1536 x 8 = 12288 B
#define SMEM_TOTAL (SMEM_B + 12288)           // 39936

__device__ float g_scores[PAIRS];

__global__ void zero_out_kernel(float* out) { out[0] = 0.0f; }

// ---------------- portable PTX helpers ----------------
__device__ __forceinline__ uint32_t pack4_e4m3(float x0, float x1, float x2, float x3) {
    uint16_t lo, hi;
    asm("cvt.rn.satfinite.e4m3x2.f32 %0, %1, %2;" : "=h"(lo) : "f"(x1), "f"(x0));
    asm("cvt.rn.satfinite.e4m3x2.f32 %0, %1, %2;" : "=h"(hi) : "f"(x3), "f"(x2));
    return (uint32_t)lo | ((uint32_t)hi << 16);
}

__device__ __forceinline__ void mma_16832_e4m3(float* c, const uint32_t* a,
                                               uint32_t b0, uint32_t b1) {
    asm volatile(
        "mma.sync.aligned.m16n8k32.row.col.f32.e4m3.e4m3.f32 "
        "{%0,%1,%2,%3}, {%4,%5,%6,%7}, {%8,%9}, {%0,%1,%2,%3};"
        : "+f"(c[0]), "+f"(c[1]), "+f"(c[2]), "+f"(c[3])
        : "r"(a[0]), "r"(a[1]), "r"(a[2]), "r"(a[3]), "r"(b0), "r"(b1));
}

__device__ __forceinline__ void store_score_cs(float* p, float v) {
    asm volatile("st.global.cs.f32 [%0], %1;" :: "l"(p), "f"(v) : "memory");
}

// ---------------------------------------------------------------------------
// Kernel 1: persistent, barrier-free warp pipelines; 8 warps x 16 m-rows.
// R13 base (125.4us) + index double-buffer (current tile's indices were
// LDG'd one tile ago -> idx-load latency off the serial chain). No prefetch.
// B (W1) packed in shared (8B LDS per fragment). fp8 mma, fp32 accumulate.
// ---------------------------------------------------------------------------
__global__ void __launch_bounds__(THREADS, 3)
score_kernel(const float* __restrict__ embeds,
             const int*   __restrict__ pos,
             const int*   __restrict__ neg,
             const float* __restrict__ W1,
             const float* __restrict__ b1,
             const float* __restrict__ W2,
             const float* __restrict__ b2)
{
    extern __shared__ char smem[];
    const int tid = threadIdx.x;
    const int wid = tid >> 5;
    const int lid = tid & 31;
    const int g   = lid >> 2;          // fragment row/col group
    const int tg  = lid & 3;           // thread-in-group

    // One-time staging: b1, W2 to shared.
    if (tid < 64) {
        ((float*)(smem + SMEM_B1))[tid] = b1[tid];
        ((float*)(smem + SMEM_W2))[tid] = W2[tid];
    }
    // Stage W1 as PACKED e4m3 fragment entries (scaled x8).
    for (int c = tid; c < 64 * 24; c += THREADS) {
        int n   = c / 24;
        int rem = c - n * 24;
        int ks  = rem >> 2;
        int tt  = rem & 3;
        int nt  = n >> 3;
        int gg  = n & 7;
        const float4* wp0 = (const float4*)(W1 + n * KDIM + ks * 32 + tt * 4);
        const float4* wp1 = (const float4*)(W1 + n * KDIM + ks * 32 + 16 + tt * 4);
        float4 w0 = *wp0, w1 = *wp1;
        uint2 v = make_uint2(
            pack4_e4m3(w0.x * 8.0f, w0.y * 8.0f, w0.z * 8.0f, w0.w * 8.0f),
            pack4_e4m3(w1.x * 8.0f, w1.y * 8.0f, w1.z * 8.0f, w1.w * 8.0f));
        int e = ((nt * 6 + ks) * 8 + gg) * 4 + tt;
        *(uint2*)(smem + SMEM_B + e * 8) = v;
    }
    __syncthreads();   // only block barrier in the kernel

    const float b2v = b2[0];
    const int q   = lid & 15;          // float4 slot within a 64-float row
    const int grp = lid >> 4;          // which of two rows per gather iter

    // ---- index loader (lanes 0..15 meaningful) ----
    auto load_idx = [&](int tile, int& iu, int& iv) {
        iu = 0; iv = 0;
        if (lid < 16) {
            int p = tile * M_TILE + wid * 16 + lid;
            unsigned e = (unsigned)p / 17u;
            unsigned jj = (unsigned)p - e * 17u;
            const int* pr = (jj == 0) ? (pos + 2 * e)
                                      : (neg + 2 * (e * KNEG + (jj - 1)));
            iu = pr[0];
            iv = pr[1];
        }
    };

    // ---- prologue: indices for tile t0 already in registers ----
    int t = blockIdx.x;
    int iuA, ivA;
    load_idx(t, iuA, ivA);

    for (; t < NTILE_TOT; t += GRID_SC) {
        const int p0 = t * M_TILE;

        // 1. issue idx load for t+G early (consumed next iteration)
        int iuN, ivN;
        {
            int tn = (t + GRID_SC < NTILE_TOT) ? t + GRID_SC : t;
            load_idx(tn, iuN, ivN);
        }

        // 2. gather + convert current tile (indices already in registers)
        #pragma unroll
        for (int bt = 0; bt < 2; bt++) {
            float4 ub[4], vb[4];
            #pragma unroll
            for (int i = 0; i < 4; i++) {
                int src = 2 * (bt * 4 + i) + grp;           // local row 0..15
                int iu = __shfl_sync(0xffffffffu, iuA, src);
                int iv = __shfl_sync(0xffffffffu, ivA, src);
                ub[i] = ((const float4*)(embeds + (size_t)iu * 64))[q];
                vb[i] = ((const float4*)(embeds + (size_t)iv * 64))[q];
            }
            #pragma unroll
            for (int i = 0; i < 4; i++) {
                int src = 2 * (bt * 4 + i) + grp;
                float4 u4 = ub[i], v4 = vb[i];
                char* xr = smem + SMEM_A + (wid * 16 + src) * APITCH;
                *(uint32_t*)(xr + q * 4) =
                    pack4_e4m3(u4.x, u4.y, u4.z, u4.w);
                *(uint32_t*)(xr + 64 + q * 4) =
                    pack4_e4m3(v4.x, v4.y, v4.z, v4.w);
                *(uint32_t*)(xr + 128 + q * 4) =
                    pack4_e4m3(u4.x * v4.x, u4.y * v4.y, u4.z * v4.z, u4.w * v4.w);
            }
        }
        __syncwarp();   // order gather STS before cross-lane fragment LDS

        // 3. GEMM: warp tile 16(m) x 64(n), K=192; B via packed 8B LDS
        float c0[NTILES][4];
        #pragma unroll
        for (int nt = 0; nt < NTILES; nt++) {
            c0[nt][0] = c0[nt][1] = c0[nt][2] = c0[nt][3] = 0.0f;
        }
        #pragma unroll
        for (int ks = 0; ks < KSTEPS; ks++) {
            uint32_t a0[4];
            {
                const char* ar = smem + SMEM_A + (wid * 16 + g) * APITCH + ks * 32 + tg * 4;
                a0[0] = *(const uint32_t*)(ar);
                a0[1] = *(const uint32_t*)(ar + 8 * APITCH);
                a0[2] = *(const uint32_t*)(ar + 16);
                a0[3] = *(const uint32_t*)(ar + 8 * APITCH + 16);
            }
            #pragma unroll
            for (int nt = 0; nt < NTILES; nt++) {
                uint2 b = *(const uint2*)(smem + SMEM_B
                                          + ((nt * 6 + ks) * 32 + lid) * 8);
                mma_16832_e4m3(c0[nt], a0, b.x, b.y);
            }
        }

        // 4. epilogue in fragment layout (x0.125 undoes the W1 x8 scale)
        const float* b1s = (const float*)(smem + SMEM_B1);
        const float* w2s = (const float*)(smem + SMEM_W2);
        float z0 = 0.0f, z1 = 0.0f;
        #pragma unroll
        for (int nt = 0; nt < NTILES; nt++) {
            int n0 = nt * 8 + 2 * tg;
            float bb0 = b1s[n0], bb1 = b1s[n0 + 1];
            float ww0 = w2s[n0], ww1 = w2s[n0 + 1];
            float h;
            h = fmaf(c0[nt][0], 0.125f, bb0); h = h > 0.0f ? h : 0.0f; z0 += h * ww0;
            h = fmaf(c0[nt][1], 0.125f, bb1); h = h > 0.0f ? h : 0.0f; z0 += h * ww1;
            h = fmaf(c0[nt][2], 0.125f, bb0); h = h > 0.0f ? h : 0.0f; z1 += h * ww0;
            h = fmaf(c0[nt][3], 0.125f, bb1); h = h > 0.0f ? h : 0.0f; z1 += h * ww1;
        }
        z0 += __shfl_xor_sync(0xffffffffu, z0, 1);
        z0 += __shfl_xor_sync(0xffffffffu, z0, 2);
        z1 += __shfl_xor_sync(0xffffffffu, z1, 1);
        z1 += __shfl_xor_sync(0xffffffffu, z1, 2);

        if (tg == 0) {
            int r = p0 + wid * 16 + g;
            float s0 = 1.0f / (1.0f + expf(-(z0 + b2v)));
            float s1 = 1.0f / (1.0f + expf(-(z1 + b2v)));
            store_score_cs(g_scores + r,     expf(s0));
            store_score_cs(g_scores + r + 8, expf(s1));
        }

        // 5. rotate index buffer
        iuA = iuN; ivA = ivN;
    }
}

// ---------------------------------------------------------------------------
// Kernel 2: per-group ratio + global reduction.
// ---------------------------------------------------------------------------
__global__ void __launch_bounds__(256)
loss_kernel(float* __restrict__ out)
{
    int e = blockIdx.x * blockDim.x + threadIdx.x;
    float term = 0.0f;
    if (e < E_GROUPS) {
        const float* s = g_scores + (long long)e * GROUP;
        float ps = s[0];
        float denom = ps;
        #pragma unroll
        for (int j = 1; j < GROUP; j++) denom += s[j];
        term = ps / (denom + 1e-8f) + 1e-8f;
    }
    #pragma unroll
    for (int o = 16; o; o >>= 1) term += __shfl_xor_sync(0xffffffffu, term, o);

    __shared__ float wsum[8];
    int l = threadIdx.x & 31;
    int w = threadIdx.x >> 5;
    if (l == 0) wsum[w] = term;
    __syncthreads();
    if (threadIdx.x < 8) {
        float t = wsum[threadIdx.x];
        #pragma unroll
        for (int o = 4; o; o >>= 1) t += __shfl_xor_sync(0x000000ffu, t, o);
        if (threadIdx.x == 0) atomicAdd(out, -t);
    }
}

extern "C" void kernel_launch(void* const* d_in, const int* in_sizes, int n_in,
                              void* d_out, int out_size)
{
    const float* embeds = (const float*)d_in[0];
    const int*   pos    = (const int*)  d_in[1];
    const int*   neg    = (const int*)  d_in[2];
    const float* W1     = (const float*)d_in[3];
    const float* b1     = (const float*)d_in[4];
    const float* W2     = (const float*)d_in[5];
    const float* b2     = (const float*)d_in[6];
    float*       out    = (float*)d_out;

    cudaFuncSetAttribute(score_kernel, cudaFuncAttributeMaxDynamicSharedMemorySize,
                         SMEM_TOTAL);

    score_kernel<<<GRID_SC, THREADS, SMEM_TOTAL>>>(embeds, pos, neg, W1, b1, W2, b2);
    zero_out_kernel<<<1, 1>>>(out);
    loss_kernel<<<E_GROUPS / 256, 256>>>(out);
}